// round 3
// baseline (speedup 1.0000x reference)
#include <cuda_runtime.h>
#include <math.h>

// Shapes: B=2, S=8192 -> R=16384 rows; H=2048; P=512; G=3P=1536; N=64 slots
#define R_ROWS   16384
#define H_DIM    2048
#define P_DIM    512
#define G_DIM    1536
#define N_SLOTS  64

// Output layout (fp32, concatenated)
#define OFF_SURPRISE 0
#define OFF_ERR      1
#define OFF_PRED     2049
#define OFF_MEM      4097
#define OFF_STR      135169
#define OFF_PSTATE   135233

// Device scratch (no cudaMalloc allowed)
__device__ __align__(16) float g_accum[H_DIM];
__device__ __align__(16) float g_actual[H_DIM];
__device__ __align__(16) float g_predicted[H_DIM];
__device__ __align__(16) float g_xgru[H_DIM];
__device__ __align__(16) float g_gi[G_DIM];
__device__ __align__(16) float g_gh[G_DIM];
__device__ float    g_surprise;
__device__ unsigned g_cnt_reduce;
__device__ unsigned g_cnt_gi;

__device__ __forceinline__ float warp_reduce_sum(float v) {
#pragma unroll
    for (int o = 16; o > 0; o >>= 1) v += __shfl_xor_sync(0xFFFFFFFFu, v, o);
    return v;
}
__device__ __forceinline__ float sigmoidf_(float x) { return 1.0f / (1.0f + expf(-x)); }

// ---------------------------------------------------------------------------
// K1 prep: block 0 zeros g_accum + counters; blocks [1,512] predicted
// (warp-per-row, K=512); blocks [513,896] gh = W_hh@pred_state + b_hh.
// All independent of the big reduction.
// ---------------------------------------------------------------------------
__global__ void k_prep(const float* __restrict__ ppw,   // (2048,512)
                       const float* __restrict__ Whh,   // (1536,512)
                       const float* __restrict__ bhh,
                       const float* __restrict__ s,     // (512,)
                       float* __restrict__ out) {
    int b = blockIdx.x, tid = threadIdx.x;
    if (b == 0) {
        float4 z = make_float4(0.f, 0.f, 0.f, 0.f);
        float4* a4 = reinterpret_cast<float4*>(g_accum);
#pragma unroll
        for (int k = 0; k < 4; k++) a4[tid + k * 128] = z;
        if (tid == 0) { g_cnt_reduce = 0u; g_cnt_gi = 0u; }
        return;
    }
    int wid = tid >> 5, lane = tid & 31;
    const float4* sv = reinterpret_cast<const float4*>(s);
    if (b <= 512) {
        int row = (b - 1) * 4 + wid;  // 0..2047
        const float4* wr = reinterpret_cast<const float4*>(ppw + (size_t)row * P_DIM);
        float acc = 0.f;
#pragma unroll
        for (int j = lane; j < P_DIM / 4; j += 32) {
            float4 w = wr[j], x = sv[j];
            acc += w.x * x.x + w.y * x.y + w.z * x.z + w.w * x.w;
        }
        acc = warp_reduce_sum(acc);
        if (lane == 0) { g_predicted[row] = acc; out[OFF_PRED + row] = acc; }
    } else {
        int row = (b - 513) * 4 + wid;  // 0..1535
        const float4* wr = reinterpret_cast<const float4*>(Whh + (size_t)row * P_DIM);
        float acc = 0.f;
#pragma unroll
        for (int j = lane; j < P_DIM / 4; j += 32) {
            float4 w = wr[j], x = sv[j];
            acc += w.x * x.x + w.y * x.y + w.z * x.z + w.w * x.w;
        }
        acc = warp_reduce_sum(acc);
        if (lane == 0) g_gh[row] = acc + bhh[row];
    }
}

// ---------------------------------------------------------------------------
// K2 reduce + finalize: 512 blocks x 512 threads, 32 rows/block, __ldcs
// streaming loads (keep weights L2-resident across replays). Last block
// computes actual, error, surprise, mem_strength.
// ---------------------------------------------------------------------------
__global__ void k_reduce_fin(const float4* __restrict__ hs,       // 16384x512 float4
                             const float* __restrict__ strength,  // (64,)
                             const int* __restrict__ wptr,
                             const float* __restrict__ scale,
                             float* __restrict__ out) {
    int tid = threadIdx.x;  // 0..511 = float4 column
    size_t base = (size_t)blockIdx.x * 32 * (H_DIM / 4) + tid;
    float ax = 0.f, ay = 0.f, az = 0.f, aw = 0.f;
#pragma unroll 8
    for (int r = 0; r < 32; r++) {
        float4 v = __ldcs(hs + base + (size_t)r * (H_DIM / 4));
        ax += v.x; ay += v.y; az += v.z; aw += v.w;
    }
    atomicAdd(&g_accum[tid * 4 + 0], ax);
    atomicAdd(&g_accum[tid * 4 + 1], ay);
    atomicAdd(&g_accum[tid * 4 + 2], az);
    atomicAdd(&g_accum[tid * 4 + 3], aw);
    __threadfence();
    __syncthreads();
    __shared__ bool last;
    if (tid == 0) last = (atomicAdd(&g_cnt_reduce, 1u) == gridDim.x - 1);
    __syncthreads();
    if (!last) return;

    // ---- finalize (512 threads, 4 columns each) ----
    const float inv = 1.0f / (float)R_ROWS;
    float4 a4 = __ldcg(reinterpret_cast<const float4*>(g_accum) + tid);
    float4 p4 = reinterpret_cast<const float4*>(g_predicted)[tid];
    float4 act;
    act.x = a4.x * inv; act.y = a4.y * inv; act.z = a4.z * inv; act.w = a4.w * inv;
    reinterpret_cast<float4*>(g_actual)[tid] = act;
    float ex = act.x - p4.x, ey = act.y - p4.y, ez = act.z - p4.z, ew = act.w - p4.w;
    float* eo = out + OFF_ERR + tid * 4;   // OFF_ERR=1: scalar stores (unaligned for v4)
    eo[0] = ex; eo[1] = ey; eo[2] = ez; eo[3] = ew;
    float local = ex * ex + ey * ey + ez * ez + ew * ew;

    __shared__ float sred[16];
    local = warp_reduce_sum(local);
    if ((tid & 31) == 0) sred[tid >> 5] = local;
    __syncthreads();
    __shared__ float s_sp;
    if (tid == 0) {
        float t = 0.f;
#pragma unroll
        for (int i = 0; i < 16; i++) t += sred[i];
        float norm = sqrtf(t) * rsqrtf((float)H_DIM);
        float sp = sigmoidf_(scale[0] * norm);
        out[OFF_SURPRISE] = sp;
        g_surprise = sp;
        s_sp = sp;
    }
    __syncthreads();
    if (tid < N_SLOTS) {
        float dec = (float)exp(8192.0 * log(0.999));  // DECAY^S
        int slot = wptr[0] % N_SLOTS;
        out[OFF_STR + tid] = (tid == slot) ? s_sp : strength[tid] * dec;
    }
}

// ---------------------------------------------------------------------------
// K3: blocks [0,2048) x_gru row (block-per-row, 128 thr, 4 float4/thr);
//     blocks [2048,2112) mem_states_new rows (copy / slot write).
// ---------------------------------------------------------------------------
__global__ void k_xgru_mem(const float* __restrict__ ipw,  // (2048,2048)
                           const float* __restrict__ mem,  // (64,2048)
                           const int* __restrict__ wptr,
                           float* __restrict__ out) {
    int b = blockIdx.x, tid = threadIdx.x;
    if (b < H_DIM) {
        const float4* wr = reinterpret_cast<const float4*>(ipw + (size_t)b * H_DIM);
        const float4* av = reinterpret_cast<const float4*>(g_actual);
        float acc = 0.f;
#pragma unroll
        for (int k = 0; k < 4; k++) {
            int j = tid + k * 128;
            float4 w = wr[j], x = av[j];
            acc += w.x * x.x + w.y * x.y + w.z * x.z + w.w * x.w;
        }
        __shared__ float s[4];
        acc = warp_reduce_sum(acc);
        if ((tid & 31) == 0) s[tid >> 5] = acc;
        __syncthreads();
        if (tid == 0) g_xgru[b] = s[0] + s[1] + s[2] + s[3];
    } else {
        int rowm = b - H_DIM;                 // 0..63
        int slot = wptr[0] % N_SLOTS;
        float sp = g_surprise;
        const float4* src = reinterpret_cast<const float4*>(mem + (size_t)rowm * H_DIM);
        const float4* av  = reinterpret_cast<const float4*>(g_actual);
#pragma unroll
        for (int k = 0; k < 4; k++) {
            int j = tid + k * 128;            // float4 index within row
            float4 v;
            if (rowm == slot) {
                float4 a = av[j];
                v.x = a.x * sp; v.y = a.y * sp; v.z = a.z * sp; v.w = a.w * sp;
            } else {
                v = src[j];
            }
            float* d = out + OFF_MEM + (size_t)rowm * H_DIM + j * 4;  // OFF_MEM odd -> scalar
            d[0] = v.x; d[1] = v.y; d[2] = v.z; d[3] = v.w;
        }
    }
}

// ---------------------------------------------------------------------------
// K4: gi = W_ih @ x_gru + b_ih (block-per-row); last block runs GRU combine.
// ---------------------------------------------------------------------------
__global__ void k_gi_gru(const float* __restrict__ Wih,  // (1536,2048)
                         const float* __restrict__ bih,
                         const float* __restrict__ pstate,
                         float* __restrict__ out) {
    int row = blockIdx.x, tid = threadIdx.x;
    const float4* wr = reinterpret_cast<const float4*>(Wih + (size_t)row * H_DIM);
    const float4* xv = reinterpret_cast<const float4*>(g_xgru);
    float acc = 0.f;
#pragma unroll
    for (int k = 0; k < 4; k++) {
        int j = tid + k * 128;
        float4 w = wr[j], x = xv[j];
        acc += w.x * x.x + w.y * x.y + w.z * x.z + w.w * x.w;
    }
    __shared__ float s[4];
    acc = warp_reduce_sum(acc);
    if ((tid & 31) == 0) s[tid >> 5] = acc;
    __syncthreads();
    __shared__ bool last;
    if (tid == 0) {
        g_gi[row] = s[0] + s[1] + s[2] + s[3] + bih[row];
        __threadfence();
        last = (atomicAdd(&g_cnt_gi, 1u) == gridDim.x - 1);
    }
    __syncthreads();
    if (!last) return;

    // ---- GRU combine (128 threads x 4 outputs) ----
#pragma unroll
    for (int k = 0; k < 4; k++) {
        int p = tid + k * 128;
        float gir = __ldcg(&g_gi[p]);
        float giz = __ldcg(&g_gi[P_DIM + p]);
        float gin = __ldcg(&g_gi[2 * P_DIM + p]);
        float r = sigmoidf_(gir + g_gh[p]);
        float z = sigmoidf_(giz + g_gh[P_DIM + p]);
        float n = tanhf(gin + r * g_gh[2 * P_DIM + p]);
        out[OFF_PSTATE + p] = (1.0f - z) * n + z * pstate[p];
    }
}

extern "C" void kernel_launch(void* const* d_in, const int* in_sizes, int n_in,
                              void* d_out, int out_size) {
    const float* hidden     = (const float*)d_in[0];
    const float* pred_state = (const float*)d_in[1];
    const float* mem_states = (const float*)d_in[2];
    const float* mem_str    = (const float*)d_in[3];
    const float* W_ih       = (const float*)d_in[4];
    const float* W_hh       = (const float*)d_in[5];
    const float* b_ih       = (const float*)d_in[6];
    const float* b_hh       = (const float*)d_in[7];
    const float* pp_w       = (const float*)d_in[8];
    const float* ip_w       = (const float*)d_in[9];
    const float* s_scale    = (const float*)d_in[10];
    const int*   write_ptr  = (const int*)d_in[11];
    float* out = (float*)d_out;

    k_prep<<<897, 128>>>(pp_w, W_hh, b_hh, pred_state, out);
    k_reduce_fin<<<512, 512>>>((const float4*)hidden, mem_str, write_ptr, s_scale, out);
    k_xgru_mem<<<2112, 128>>>(ip_w, mem_states, write_ptr, out);
    k_gi_gru<<<1536, 128>>>(W_ih, b_ih, pred_state, out);
}

// round 4
// speedup vs baseline: 1.5424x; 1.5424x over previous
#include <cuda_runtime.h>
#include <math.h>

// Shapes: B=2, S=8192 -> R=16384 rows; H=2048 (=512 float4); P=512; 3P=1536; 64 slots
#define GRID     148
#define TPB      1024
#define R_ROWS   16384
#define H_DIM    2048
#define H4       512
#define P_DIM    512
#define G_DIM    1536
#define N_SLOTS  64

// Output layout (fp32, concatenated)
#define OFF_SURPRISE 0
#define OFF_ERR      1
#define OFF_PRED     2049
#define OFF_MEM      4097
#define OFF_STR      135169
#define OFF_PSTATE   135233

// Device scratch
__device__ __align__(16) float4 g_part[128 * H4];   // per-block reduce partials (1MB)
__device__ __align__(16) float  g_actual[H_DIM];
__device__ __align__(16) float  g_predicted[H_DIM];
__device__ __align__(16) float  g_xgru[H_DIM];
__device__ __align__(16) float  g_gi[G_DIM];
__device__ __align__(16) float  g_gh[G_DIM];
__device__ float    g_sumsq;
__device__ unsigned g_count   = 0;   // barrier arrivals (self-resetting)
__device__ unsigned g_release = 0;   // barrier release flag; toggles 1,0,1,0 -> ends 0

__device__ __forceinline__ float warp_sum(float v) {
#pragma unroll
    for (int o = 16; o > 0; o >>= 1) v += __shfl_xor_sync(0xFFFFFFFFu, v, o);
    return v;
}
__device__ __forceinline__ float sigmoidf_(float x) { return 1.0f / (1.0f + expf(-x)); }

// Grid-wide barrier. All 148 blocks are co-resident (1 block/SM guaranteed by
// __launch_bounds__(1024,1)), so spinning is deadlock-free. Last arriver resets
// the count and flips the release flag to `expect`. Expect sequence 1,0,1,0
// restores g_release to 0 for the next (identical) graph replay.
__device__ __forceinline__ void grid_bar(unsigned expect) {
    __syncthreads();
    if (threadIdx.x == 0) {
        __threadfence();
        unsigned t = atomicAdd(&g_count, 1u);
        if (t == GRID - 1) {
            atomicExch(&g_count, 0u);
            __threadfence();
            atomicExch(&g_release, expect);
        } else {
            while (*(volatile unsigned*)&g_release != expect) __nanosleep(64);
        }
        __threadfence();
    }
    __syncthreads();
}

__global__ void __launch_bounds__(TPB, 1)
k_fused(const float4* __restrict__ hs,       // hidden_states as float4 (16384 x 512)
        const float*  __restrict__ pstate,   // (512,)
        const float4* __restrict__ mem4,     // mem_states as float4 (64 x 512)
        const float*  __restrict__ strength, // (64,)
        const float*  __restrict__ Wih,      // (1536,2048)
        const float*  __restrict__ Whh,      // (1536,512)
        const float*  __restrict__ bih,
        const float*  __restrict__ bhh,
        const float*  __restrict__ ppw,      // (2048,512)
        const float*  __restrict__ ipw,      // (2048,2048)
        const float*  __restrict__ scale,
        const int*    __restrict__ wptr,
        float* __restrict__ out) {
    __shared__ float4 shv[H4];      // 8KB: reduce-halves combine / staged x vectors
    __shared__ float4 sfin[16];

    const int b = blockIdx.x, t = threadIdx.x;
    const int lane = t & 31, w = t >> 5;

    // ===================== Phase A (fully parallel) =========================
    if (b < 128) {
        // Big reduction: block b sums rows [b*128, b*128+128) into g_part[b].
        const int c = t & 511;            // float4 column
        const int half = t >> 9;          // 0/1: which 64-row half
        size_t base = (size_t)(b * 128 + half * 64) * H4 + c;
        float4 a0 = make_float4(0.f,0.f,0.f,0.f), a1 = a0;
#pragma unroll 8
        for (int k = 0; k < 64; k += 2) {
            float4 v0 = __ldcs(hs + base + (size_t)k * H4);
            float4 v1 = __ldcs(hs + base + (size_t)(k + 1) * H4);
            a0.x += v0.x; a0.y += v0.y; a0.z += v0.z; a0.w += v0.w;
            a1.x += v1.x; a1.y += v1.y; a1.z += v1.z; a1.w += v1.w;
        }
        float4 a; a.x = a0.x + a1.x; a.y = a0.y + a1.y; a.z = a0.z + a1.z; a.w = a0.w + a1.w;
        if (half) shv[c] = a;
        __syncthreads();
        if (!half) {
            float4 o = shv[c];
            a.x += o.x; a.y += o.y; a.z += o.z; a.w += o.w;
            g_part[b * H4 + c] = a;
        }
    } else if (b < 138) {
        // predicted = pred_proj_w @ pred_state (2048 rows, K=512), warp-per-row
        int ws = (b - 128) * 32 + w;                       // 0..319
        const float4* s4 = reinterpret_cast<const float4*>(pstate);
        for (int row = ws; row < H_DIM; row += 320) {
            const float4* wr = reinterpret_cast<const float4*>(ppw + (size_t)row * P_DIM);
            float acc = 0.f;
#pragma unroll
            for (int j = 0; j < 4; j++) {
                float4 wv = wr[lane + 32 * j];
                float4 xv = __ldg(s4 + lane + 32 * j);
                acc += wv.x * xv.x + wv.y * xv.y + wv.z * xv.z + wv.w * xv.w;
            }
            acc = warp_sum(acc);
            if (lane == 0) { g_predicted[row] = acc; out[OFF_PRED + row] = acc; }
        }
    } else if (b < 146) {
        // gh = W_hh @ pred_state + b_hh (1536 rows, K=512), warp-per-row
        int ws = (b - 138) * 32 + w;                       // 0..255
        const float4* s4 = reinterpret_cast<const float4*>(pstate);
        for (int row = ws; row < G_DIM; row += 256) {
            const float4* wr = reinterpret_cast<const float4*>(Whh + (size_t)row * P_DIM);
            float acc = 0.f;
#pragma unroll
            for (int j = 0; j < 4; j++) {
                float4 wv = wr[lane + 32 * j];
                float4 xv = __ldg(s4 + lane + 32 * j);
                acc += wv.x * xv.x + wv.y * xv.y + wv.z * xv.z + wv.w * xv.w;
            }
            acc = warp_sum(acc);
            if (lane == 0) g_gh[row] = acc + bhh[row];
        }
    } else {
        // mem_states copy (63 non-slot rows) + sumsq zero
        int gid = (b - 146) * TPB + t;                     // 0..2047
        int slot = wptr[0] & (N_SLOTS - 1);
#pragma unroll
        for (int k = 0; k < 16; k++) {
            int idx = gid + k * 2048;                      // float4 idx 0..32767
            int row = idx >> 9;
            if (row != slot) {
                float4 v = __ldg(mem4 + idx);
                float* d = out + OFF_MEM + (size_t)idx * 4;
                d[0] = v.x; d[1] = v.y; d[2] = v.z; d[3] = v.w;
            }
        }
        if (b == 147 && t == 0) g_sumsq = 0.f;
    }

    grid_bar(1);

    // ===================== Phase B: finalize columns ========================
    if (b < 128) {
        // block b owns float4 columns [b*4, b*4+4); 128 partials each.
        int cslot = t >> 7;       // 0..7 (only 0..3 active)
        int p = t & 127;
        float4 s = make_float4(0.f,0.f,0.f,0.f);
        int col = b * 4 + cslot;
        if (cslot < 4) s = g_part[p * H4 + col];
#pragma unroll
        for (int o = 16; o > 0; o >>= 1) {
            s.x += __shfl_xor_sync(0xFFFFFFFFu, s.x, o);
            s.y += __shfl_xor_sync(0xFFFFFFFFu, s.y, o);
            s.z += __shfl_xor_sync(0xFFFFFFFFu, s.z, o);
            s.w += __shfl_xor_sync(0xFFFFFFFFu, s.w, o);
        }
        if (cslot < 4 && lane == 0) sfin[cslot * 4 + (w & 3)] = s;
        __syncthreads();
        if (cslot < 4 && (t & 127) == 0) {
            float4 a = make_float4(0.f,0.f,0.f,0.f);
#pragma unroll
            for (int i = 0; i < 4; i++) {
                float4 v = sfin[cslot * 4 + i];
                a.x += v.x; a.y += v.y; a.z += v.z; a.w += v.w;
            }
            const float inv = 1.0f / (float)R_ROWS;
            a.x *= inv; a.y *= inv; a.z *= inv; a.w *= inv;
            reinterpret_cast<float4*>(g_actual)[col] = a;
            float4 pd = reinterpret_cast<const float4*>(g_predicted)[col];
            float ex = a.x - pd.x, ey = a.y - pd.y, ez = a.z - pd.z, ew = a.w - pd.w;
            float* eo = out + OFF_ERR + col * 4;
            eo[0] = ex; eo[1] = ey; eo[2] = ez; eo[3] = ew;
            atomicAdd(&g_sumsq, ex * ex + ey * ey + ez * ez + ew * ew);
        }
    }

    grid_bar(0);

    // ===================== Phase C: x_gru + surprise-dependent outs =========
    if (t < H4) shv[t] = reinterpret_cast<const float4*>(g_actual)[t];
    __syncthreads();
    {
        int ws = b * 32 + w;    // global warp slot
        if (ws < H_DIM) {
            const float4* wr = reinterpret_cast<const float4*>(ipw + (size_t)ws * H_DIM);
            float acc = 0.f;
#pragma unroll
            for (int j = 0; j < 16; j++) {
                float4 wv = wr[lane + 32 * j];
                float4 xv = shv[lane + 32 * j];
                acc += wv.x * xv.x + wv.y * xv.y + wv.z * xv.z + wv.w * xv.w;
            }
            acc = warp_sum(acc);
            if (lane == 0) g_xgru[ws] = acc;
        } else if (ws < H_DIM + 35) {
            float sp = sigmoidf_(scale[0] * sqrtf(g_sumsq) * rsqrtf((float)H_DIM));
            int slot = wptr[0] & (N_SLOTS - 1);
            if (ws < H_DIM + 32) {
                // slot row of mem_states_new: actual * surprise (32 warps x 64 floats)
                int i = (ws - H_DIM) * 64 + lane * 2;
                float2 a = *reinterpret_cast<const float2*>(g_actual + i);
                float* d = out + OFF_MEM + (size_t)slot * H_DIM + i;
                d[0] = a.x * sp; d[1] = a.y * sp;
            } else if (ws < H_DIM + 34) {
                int i = (ws - (H_DIM + 32)) * 32 + lane;   // 0..63
                float dec = (float)exp(8192.0 * log(0.999));
                out[OFF_STR + i] = (i == slot) ? sp : strength[i] * dec;
            } else if (lane == 0) {
                out[OFF_SURPRISE] = sp;
            }
        }
    }

    grid_bar(1);

    // ===================== Phase D: gi = W_ih @ x_gru + b_ih ================
    if (t < H4) shv[t] = reinterpret_cast<const float4*>(g_xgru)[t];
    __syncthreads();
    {
        int ws = b * 32 + w;
        if (ws < G_DIM) {
            const float4* wr = reinterpret_cast<const float4*>(Wih + (size_t)ws * H_DIM);
            float acc = 0.f;
#pragma unroll
            for (int j = 0; j < 16; j++) {
                float4 wv = wr[lane + 32 * j];
                float4 xv = shv[lane + 32 * j];
                acc += wv.x * xv.x + wv.y * xv.y + wv.z * xv.z + wv.w * xv.w;
            }
            acc = warp_sum(acc);
            if (lane == 0) g_gi[ws] = acc + bih[ws];
        }
    }

    grid_bar(0);

    // ===================== Phase E: GRU combine (block 0) ===================
    if (b == 0 && t < P_DIM) {
        float r = sigmoidf_(g_gi[t]             + g_gh[t]);
        float z = sigmoidf_(g_gi[P_DIM + t]     + g_gh[P_DIM + t]);
        float n = tanhf(g_gi[2 * P_DIM + t] + r * g_gh[2 * P_DIM + t]);
        out[OFF_PSTATE + t] = (1.0f - z) * n + z * pstate[t];
    }
}

extern "C" void kernel_launch(void* const* d_in, const int* in_sizes, int n_in,
                              void* d_out, int out_size) {
    const float* hidden     = (const float*)d_in[0];
    const float* pred_state = (const float*)d_in[1];
    const float* mem_states = (const float*)d_in[2];
    const float* mem_str    = (const float*)d_in[3];
    const float* W_ih       = (const float*)d_in[4];
    const float* W_hh       = (const float*)d_in[5];
    const float* b_ih       = (const float*)d_in[6];
    const float* b_hh       = (const float*)d_in[7];
    const float* pp_w       = (const float*)d_in[8];
    const float* ip_w       = (const float*)d_in[9];
    const float* s_scale    = (const float*)d_in[10];
    const int*   write_ptr  = (const int*)d_in[11];
    float* out = (float*)d_out;

    k_fused<<<GRID, TPB>>>((const float4*)hidden, pred_state,
                           (const float4*)mem_states, mem_str,
                           W_ih, W_hh, b_ih, b_hh, pp_w, ip_w,
                           s_scale, write_ptr, out);
}